// round 6
// baseline (speedup 1.0000x reference)
#include <cuda_runtime.h>
#include <cuda_bf16.h>
#include <cstdint>

// out[b,h,i,j] = scores[b,h,i,j] + sum_d q[b,h,i,d] * emb[j-i+4096, d]
// Per 64(i) x 128(j) tile: G[64 x 192] = Q @ E_window^T, bf16 hi/lo 3-pass
// mma.sync GEMM; scores tile prefetched via cp.async DURING the GEMM so the
// combine phase is SMEM + store only.

#define S_LEN 2048
#define D_HEAD 64
#define TI 64
#define TJ 128
#define NB 192
#define HALF 4096
#define GS 197          // staging stride (words), == 1 mod 4 -> aligned LDS.128

#define OFF_QH 0        // 64 x 128B bf16-hi (XOR-swizzled 16B chunks)
#define OFF_QL 8192
#define OFF_EH 16384    // 192 x 128B
#define OFF_EL 40960
#define OFF_S  65536    // scores tile 64x128 fp32 (cp.async target)
#define SMEM_TOTAL 98304
// G staging: 64 x GS words fp32 = 50432 B, reuses [0, 64K) after GEMM.

static __device__ __forceinline__ uint32_t smem_u32(const void* p) {
    uint32_t a;
    asm("{ .reg .u64 t; cvta.to.shared.u64 t, %1; cvt.u32.u64 %0, t; }"
        : "=r"(a) : "l"(p));
    return a;
}
static __device__ __forceinline__ uint32_t pack_bf16(float x, float y) {
    return (uint32_t)__bfloat16_as_ushort(__float2bfloat16_rn(x)) |
           ((uint32_t)__bfloat16_as_ushort(__float2bfloat16_rn(y)) << 16);
}
static __device__ __forceinline__ void store_hilo(uint32_t hi_addr, uint32_t lo_addr,
                                                  float4 v) {
    float hx = __bfloat162float(__float2bfloat16_rn(v.x));
    float hy = __bfloat162float(__float2bfloat16_rn(v.y));
    float hz = __bfloat162float(__float2bfloat16_rn(v.z));
    float hw = __bfloat162float(__float2bfloat16_rn(v.w));
    uint32_t h01 = pack_bf16(v.x, v.y), h23 = pack_bf16(v.z, v.w);
    uint32_t l01 = pack_bf16(v.x - hx, v.y - hy), l23 = pack_bf16(v.z - hz, v.w - hw);
    asm volatile("st.shared.v2.b32 [%0], {%1,%2};" :: "r"(hi_addr), "r"(h01), "r"(h23) : "memory");
    asm volatile("st.shared.v2.b32 [%0], {%1,%2};" :: "r"(lo_addr), "r"(l01), "r"(l23) : "memory");
}

__global__ __launch_bounds__(256, 2)
void relpos_mma3_kernel(const float* __restrict__ q,
                        const float* __restrict__ scores,
                        const float* __restrict__ emb,
                        float* __restrict__ out)
{
    extern __shared__ char smem[];
    const uint32_t sb = smem_u32(smem);
    const int tid = threadIdx.x, wid = tid >> 5, lane = tid & 31;
    const int bh = blockIdx.z, i0 = blockIdx.y * TI, j0 = blockIdx.x * TJ;

    // ---- Load + convert Q [64 x 64] -> Qhi/Qlo ----
    {
        const float* qb = q + ((size_t)bh * S_LEN + i0) * D_HEAD;
        #pragma unroll
        for (int it = 0; it < 4; it++) {
            int u = it * 256 + tid;
            int row = u >> 4, g = u & 15;
            float4 v = __ldg((const float4*)(qb + (size_t)row * D_HEAD) + g);
            uint32_t off = (uint32_t)(row * 128 + (((g >> 1) ^ (row & 7)) << 4) + (g & 1) * 8);
            store_hilo(sb + OFF_QH + off, sb + OFF_QL + off, v);
        }
    }
    // ---- Load + convert E window [192 x 64] -> Ehi/Elo ----
    {
        const int e0 = j0 - i0 + HALF - (TI - 1);   // [2049, 5953]; +191 in-bounds
        const float* eb = emb + (size_t)e0 * D_HEAD;
        #pragma unroll
        for (int it = 0; it < 12; it++) {
            int u = it * 256 + tid;
            int row = u >> 4, g = u & 15;
            float4 v = __ldg((const float4*)(eb + (size_t)row * D_HEAD) + g);
            uint32_t off = (uint32_t)(row * 128 + (((g >> 1) ^ (row & 7)) << 4) + (g & 1) * 8);
            store_hilo(sb + OFF_EH + off, sb + OFF_EL + off, v);
        }
    }
    __syncthreads();

    // ---- Kick scores prefetch (gmem -> SMEM, async; overlaps GEMM) ----
    {
        const float* sbase = scores + ((size_t)bh * S_LEN + i0) * S_LEN + j0;
        #pragma unroll
        for (int it = 0; it < 8; it++) {
            int u = it * 256 + tid;                  // 2048 float4 units
            int row = u >> 5, c4 = u & 31;
            uint32_t dst = sb + OFF_S + (uint32_t)(u << 4);
            const float4* src = (const float4*)(sbase + (size_t)row * S_LEN) + c4;
            asm volatile("cp.async.cg.shared.global [%0], [%1], 16;"
                         :: "r"(dst), "l"(src) : "memory");
        }
        asm volatile("cp.async.commit_group;" ::: "memory");
    }

    // ---- GEMM: warp (mg, nh) -> rows [32mg,+32) x cols [48nh,+48) ----
    const int mg = wid >> 2, nh = wid & 3;
    const int m0 = mg * 32, n0 = nh * 48;
    float c[2][6][4];
    #pragma unroll
    for (int mf = 0; mf < 2; mf++)
        #pragma unroll
        for (int f = 0; f < 6; f++)
            #pragma unroll
            for (int k = 0; k < 4; k++) c[mf][f][k] = 0.0f;

    const int a_rl = (lane & 7) + ((lane >> 3) & 1) * 8;
    const int a_ch = lane >> 4;
    const int b_rl = lane & 7;
    const int b_nf = lane >> 4;
    const int b_ch = (lane >> 3) & 1;

    #pragma unroll 1
    for (int pass = 0; pass < 3; pass++) {
        const uint32_t Ab = sb + (pass < 2 ? OFF_QH : OFF_QL);
        const uint32_t Bb = sb + (pass == 1 ? OFF_EL : OFF_EH);
        #pragma unroll
        for (int ks = 0; ks < 4; ks++) {
            uint32_t a[2][4];
            #pragma unroll
            for (int mf = 0; mf < 2; mf++) {
                int row = m0 + mf * 16 + a_rl;
                int ch = (2 * ks + a_ch) ^ (row & 7);
                uint32_t addr = Ab + (uint32_t)(row * 128 + ch * 16);
                asm volatile("ldmatrix.sync.aligned.m8n8.x4.shared.b16 {%0,%1,%2,%3}, [%4];"
                             : "=r"(a[mf][0]), "=r"(a[mf][1]), "=r"(a[mf][2]), "=r"(a[mf][3])
                             : "r"(addr));
            }
            #pragma unroll
            for (int bp = 0; bp < 3; bp++) {
                int nrow = n0 + (2 * bp + b_nf) * 8 + b_rl;
                int ch = (2 * ks + b_ch) ^ (nrow & 7);
                uint32_t addr = Bb + (uint32_t)(nrow * 128 + ch * 16);
                uint32_t b0, b1, b2, b3;
                asm volatile("ldmatrix.sync.aligned.m8n8.x4.shared.b16 {%0,%1,%2,%3}, [%4];"
                             : "=r"(b0), "=r"(b1), "=r"(b2), "=r"(b3) : "r"(addr));
                #pragma unroll
                for (int mf = 0; mf < 2; mf++) {
                    asm volatile("mma.sync.aligned.m16n8k16.row.col.f32.bf16.bf16.f32 "
                                 "{%0,%1,%2,%3}, {%4,%5,%6,%7}, {%8,%9}, {%0,%1,%2,%3};"
                                 : "+f"(c[mf][2*bp][0]), "+f"(c[mf][2*bp][1]),
                                   "+f"(c[mf][2*bp][2]), "+f"(c[mf][2*bp][3])
                                 : "r"(a[mf][0]), "r"(a[mf][1]), "r"(a[mf][2]), "r"(a[mf][3]),
                                   "r"(b0), "r"(b1));
                    asm volatile("mma.sync.aligned.m16n8k16.row.col.f32.bf16.bf16.f32 "
                                 "{%0,%1,%2,%3}, {%4,%5,%6,%7}, {%8,%9}, {%0,%1,%2,%3};"
                                 : "+f"(c[mf][2*bp+1][0]), "+f"(c[mf][2*bp+1][1]),
                                   "+f"(c[mf][2*bp+1][2]), "+f"(c[mf][2*bp+1][3])
                                 : "r"(a[mf][0]), "r"(a[mf][1]), "r"(a[mf][2]), "r"(a[mf][3]),
                                   "r"(b2), "r"(b3));
                }
            }
        }
    }
    __syncthreads();   // all GEMM reads of operand SMEM done
    asm volatile("cp.async.wait_group 0;" ::: "memory");  // scores landed (this thread)

    // ---- Stage G to skewed SMEM: word(row,col) = row*GS + 1 + col ----
    {
        #pragma unroll
        for (int mf = 0; mf < 2; mf++) {
            int r0 = m0 + mf * 16 + (lane >> 2);
            #pragma unroll
            for (int nf = 0; nf < 6; nf++) {
                int col = n0 + nf * 8 + 2 * (lane & 3);
                uint32_t w0 = sb + (uint32_t)((r0 * GS + 1 + col) << 2);
                uint32_t w1 = w0 + (uint32_t)(8 * GS * 4);
                asm volatile("st.shared.b32 [%0], %1;" :: "r"(w0),     "f"(c[mf][nf][0]) : "memory");
                asm volatile("st.shared.b32 [%0], %1;" :: "r"(w0 + 4), "f"(c[mf][nf][1]) : "memory");
                asm volatile("st.shared.b32 [%0], %1;" :: "r"(w1),     "f"(c[mf][nf][2]) : "memory");
                asm volatile("st.shared.b32 [%0], %1;" :: "r"(w1 + 4), "f"(c[mf][nf][3]) : "memory");
            }
        }
    }
    __syncthreads();   // staging done AND every thread's scores cp.async waited

    // ---- Combine: out[row][jj] = scoresS[row][jj] + G[row][jj - row + 63] ----
    // staged word = row*(GS-1) + 64 + jj   (aligned float4: GS-1 % 4 == 0)
    {
        const float* Gw = (const float*)smem;
        const float* Ss = (const float*)(smem + OFF_S);
        const size_t srow = (size_t)bh * S_LEN + (size_t)i0;
        #pragma unroll
        for (int rr = 0; rr < 8; rr++) {
            int row = wid * 8 + rr;
            float4 g = *(const float4*)(Gw + row * (GS - 1) + 64 + 4 * lane);
            float4 s = *(const float4*)(Ss + row * 128 + 4 * lane);
            float4 o = make_float4(s.x + g.x, s.y + g.y, s.z + g.z, s.w + g.w);
            *(float4*)(out + (srow + row) * S_LEN + (size_t)(j0 + 4 * lane)) = o;
        }
    }
}

extern "C" void kernel_launch(void* const* d_in, const int* in_sizes, int n_in,
                              void* d_out, int out_size)
{
    const float* q      = (const float*)d_in[0];  // [2,16,2048,64]
    const float* scores = (const float*)d_in[1];  // [2,16,2048,2048]
    const float* emb    = (const float*)d_in[2];  // [8192,64]
    float* out = (float*)d_out;

    cudaFuncSetAttribute(relpos_mma3_kernel,
                         cudaFuncAttributeMaxDynamicSharedMemorySize, SMEM_TOTAL);
    dim3 grid(S_LEN / TJ, S_LEN / TI, 32);   // (16, 32, 32) = 16384 CTAs
    relpos_mma3_kernel<<<grid, 256, SMEM_TOTAL>>>(q, scores, emb, out);
}